// round 1
// baseline (speedup 1.0000x reference)
#include <cuda_runtime.h>
#include <cuda_bf16.h>
#include <math.h>

// Shapes (fixed by the problem)
//  B=32, N=1024, D=512, E=1024, S=128
//  rows = B*N = 32768
//  uv cols = 2E+S = 2176

#define ROWS 32768
#define DD   512
#define EE   1024
#define SS   128
#define NB   32
#define NN   1024
#define UVC  2176

// -------------------- scratch (no allocations allowed) --------------------
__device__ float g_scale[ROWS];                       // g / max(||x||, eps)
__device__ float g_u[(size_t)ROWS * EE];              // 134 MB
__device__ float g_v[(size_t)ROWS * EE];              // 134 MB
__device__ float g_q[(size_t)ROWS * SS];              // 16.8 MB
__device__ float g_k[(size_t)ROWS * SS];              // 16.8 MB
__device__ float g_attn[(size_t)NB * NN * NN];        // 134 MB
__device__ float g_mid[(size_t)ROWS * EE];            // 134 MB

// -------------------- row norm --------------------
// one warp per row, D=512 -> 16 elems/lane
__global__ __launch_bounds__(256) void rownorm_kernel(const float* __restrict__ x,
                                                      const float* __restrict__ gptr)
{
    int row  = blockIdx.x * 8 + (threadIdx.x >> 5);
    int lane = threadIdx.x & 31;
    const float* xr = x + (size_t)row * DD;
    float s = 0.f;
#pragma unroll
    for (int t = 0; t < 16; t++) {
        float v = xr[lane + 32 * t];
        s = fmaf(v, v, s);
    }
#pragma unroll
    for (int o = 16; o; o >>= 1) s += __shfl_xor_sync(0xffffffffu, s, o);
    if (lane == 0) g_scale[row] = gptr[0] / fmaxf(sqrtf(s), 1e-5f);
}

// ==========================================================================
// GEMM 1: uv = silu( (x * scale_row) @ uv_w )  [32768 x 2176, K=512]
// epilogue scatters u, v and builds q,k with gamma/beta.
// ==========================================================================
__global__ __launch_bounds__(256) void gemm_uv(const float* __restrict__ x,
                                               const float* __restrict__ uvw,
                                               const float* __restrict__ gamma,
                                               const float* __restrict__ beta)
{
    __shared__ float As[16][132];
    __shared__ float Bs[16][128];
    __shared__ float sS[128];
    const int row0 = blockIdx.y * 128;
    const int col0 = blockIdx.x * 128;
    const int tid  = threadIdx.x;
    const int tx   = tid & 15, ty = tid >> 4;

    if (tid < 128) sS[tid] = g_scale[row0 + tid];

    float acc[8][8];
#pragma unroll
    for (int i = 0; i < 8; i++)
#pragma unroll
        for (int j = 0; j < 8; j++) acc[i][j] = 0.f;

    for (int k0 = 0; k0 < DD; k0 += 16) {
        __syncthreads();
#pragma unroll
        for (int li = 0; li < 2; li++) {
            int f4 = tid + li * 256;
            // A tile: 128 rows x 16 cols (4 float4 per row)
            int r = f4 >> 2, c = (f4 & 3) << 2;
            float4 av = *(const float4*)(x + (size_t)(row0 + r) * DD + k0 + c);
            float s = sS[r];
            As[c + 0][r] = av.x * s;
            As[c + 1][r] = av.y * s;
            As[c + 2][r] = av.z * s;
            As[c + 3][r] = av.w * s;
            // B tile: 16 rows x 128 cols (32 float4 per row)
            int rb = f4 >> 5, cb = (f4 & 31) << 2;
            float4 bv = *(const float4*)(uvw + (size_t)(k0 + rb) * UVC + col0 + cb);
            *(float4*)&Bs[rb][cb] = bv;
        }
        __syncthreads();
#pragma unroll
        for (int kk = 0; kk < 16; kk++) {
            float a[8], b[8];
            *(float4*)(a)     = *(const float4*)&As[kk][ty * 8];
            *(float4*)(a + 4) = *(const float4*)&As[kk][ty * 8 + 4];
            *(float4*)(b)     = *(const float4*)&Bs[kk][tx * 8];
            *(float4*)(b + 4) = *(const float4*)&Bs[kk][tx * 8 + 4];
#pragma unroll
            for (int i = 0; i < 8; i++)
#pragma unroll
                for (int j = 0; j < 8; j++) acc[i][j] = fmaf(a[i], b[j], acc[i][j]);
        }
    }

#pragma unroll
    for (int i = 0; i < 8; i++) {
        int row = row0 + ty * 8 + i;
#pragma unroll
        for (int j = 0; j < 8; j++) {
            int col = col0 + tx * 8 + j;
            float c  = acc[i][j];
            float sv = c / (1.f + __expf(-c));   // silu
            if (col < EE) {
                g_u[(size_t)row * EE + col] = sv;
            } else if (col < 2 * EE) {
                g_v[(size_t)row * EE + (col - EE)] = sv;
            } else {
                int s = col - 2 * EE;
                g_q[(size_t)row * SS + s] = fmaf(sv, gamma[s],      beta[s]);
                g_k[(size_t)row * SS + s] = fmaf(sv, gamma[SS + s], beta[SS + s]);
            }
        }
    }
}

// ==========================================================================
// GEMM 2 (batched, NT): attn = relu((q k^T + w_bias)/sqrt(S))^2
// per batch: 1024 x 1024, K = 128
// ==========================================================================
__global__ __launch_bounds__(256) void gemm_qk(const float* __restrict__ w)
{
    __shared__ float As[16][132];
    __shared__ float Bs[16][132];
    const int b    = blockIdx.z;
    const int row0 = blockIdx.y * 128;
    const int col0 = blockIdx.x * 128;
    const int tid  = threadIdx.x;
    const int tx   = tid & 15, ty = tid >> 4;
    const float* qb = g_q + (size_t)b * NN * SS;
    const float* kb = g_k + (size_t)b * NN * SS;

    float acc[8][8];
#pragma unroll
    for (int i = 0; i < 8; i++)
#pragma unroll
        for (int j = 0; j < 8; j++) acc[i][j] = 0.f;

    for (int k0 = 0; k0 < SS; k0 += 16) {
        __syncthreads();
#pragma unroll
        for (int li = 0; li < 2; li++) {
            int f4 = tid + li * 256;
            int r = f4 >> 2, c = (f4 & 3) << 2;
            float4 av = *(const float4*)(qb + (size_t)(row0 + r) * SS + k0 + c);
            As[c + 0][r] = av.x; As[c + 1][r] = av.y;
            As[c + 2][r] = av.z; As[c + 3][r] = av.w;
            float4 bv = *(const float4*)(kb + (size_t)(col0 + r) * SS + k0 + c);
            Bs[c + 0][r] = bv.x; Bs[c + 1][r] = bv.y;
            Bs[c + 2][r] = bv.z; Bs[c + 3][r] = bv.w;
        }
        __syncthreads();
#pragma unroll
        for (int kk = 0; kk < 16; kk++) {
            float a[8], bb[8];
            *(float4*)(a)      = *(const float4*)&As[kk][ty * 8];
            *(float4*)(a + 4)  = *(const float4*)&As[kk][ty * 8 + 4];
            *(float4*)(bb)     = *(const float4*)&Bs[kk][tx * 8];
            *(float4*)(bb + 4) = *(const float4*)&Bs[kk][tx * 8 + 4];
#pragma unroll
            for (int i = 0; i < 8; i++)
#pragma unroll
                for (int j = 0; j < 8; j++) acc[i][j] = fmaf(a[i], bb[j], acc[i][j]);
        }
    }

    float* ab = g_attn + (size_t)b * NN * NN;
    const float inv_sqrt_s = 0.088388347648318447f;  // 1/sqrt(128)
#pragma unroll
    for (int i = 0; i < 8; i++) {
        int m = row0 + ty * 8 + i;
#pragma unroll
        for (int j = 0; j < 8; j++) {
            int n = col0 + tx * 8 + j;
            float t = (acc[i][j] + w[NN - 1 + n - m]) * inv_sqrt_s;
            t = fmaxf(t, 0.f);
            ab[(size_t)m * NN + n] = t * t;
        }
    }
}

// ==========================================================================
// GEMM 3 (batched, NN): mid = u * (attn @ v)   per batch 1024 x 1024, K=1024
// ==========================================================================
__global__ __launch_bounds__(256) void gemm_av()
{
    __shared__ float As[16][132];
    __shared__ float Bs[16][128];
    const int b    = blockIdx.z;
    const int row0 = blockIdx.y * 128;
    const int col0 = blockIdx.x * 128;
    const int tid  = threadIdx.x;
    const int tx   = tid & 15, ty = tid >> 4;
    const float* A  = g_attn + (size_t)b * NN * NN;
    const float* Bm = g_v    + (size_t)b * NN * EE;

    float acc[8][8];
#pragma unroll
    for (int i = 0; i < 8; i++)
#pragma unroll
        for (int j = 0; j < 8; j++) acc[i][j] = 0.f;

    for (int k0 = 0; k0 < NN; k0 += 16) {
        __syncthreads();
#pragma unroll
        for (int li = 0; li < 2; li++) {
            int f4 = tid + li * 256;
            int r = f4 >> 2, c = (f4 & 3) << 2;
            float4 av = *(const float4*)(A + (size_t)(row0 + r) * NN + k0 + c);
            As[c + 0][r] = av.x; As[c + 1][r] = av.y;
            As[c + 2][r] = av.z; As[c + 3][r] = av.w;
            int rb = f4 >> 5, cb = (f4 & 31) << 2;
            float4 bv = *(const float4*)(Bm + (size_t)(k0 + rb) * EE + col0 + cb);
            *(float4*)&Bs[rb][cb] = bv;
        }
        __syncthreads();
#pragma unroll
        for (int kk = 0; kk < 16; kk++) {
            float a[8], bb[8];
            *(float4*)(a)      = *(const float4*)&As[kk][ty * 8];
            *(float4*)(a + 4)  = *(const float4*)&As[kk][ty * 8 + 4];
            *(float4*)(bb)     = *(const float4*)&Bs[kk][tx * 8];
            *(float4*)(bb + 4) = *(const float4*)&Bs[kk][tx * 8 + 4];
#pragma unroll
            for (int i = 0; i < 8; i++)
#pragma unroll
                for (int j = 0; j < 8; j++) acc[i][j] = fmaf(a[i], bb[j], acc[i][j]);
        }
    }

#pragma unroll
    for (int i = 0; i < 8; i++) {
        size_t row = (size_t)b * NN + row0 + ty * 8 + i;
#pragma unroll
        for (int j = 0; j < 8; j++) {
            int col = col0 + tx * 8 + j;
            size_t idx = row * EE + col;
            g_mid[idx] = g_u[idx] * acc[i][j];
        }
    }
}

// ==========================================================================
// GEMM 4: out = x*res_scale + mid @ o_w   [32768 x 512, K=1024]
// ==========================================================================
__global__ __launch_bounds__(256) void gemm_final(const float* __restrict__ x,
                                                  const float* __restrict__ ow,
                                                  const float* __restrict__ res_scale,
                                                  float* __restrict__ out)
{
    __shared__ float As[16][132];
    __shared__ float Bs[16][128];
    const int row0 = blockIdx.y * 128;
    const int col0 = blockIdx.x * 128;
    const int tid  = threadIdx.x;
    const int tx   = tid & 15, ty = tid >> 4;

    float acc[8][8];
#pragma unroll
    for (int i = 0; i < 8; i++)
#pragma unroll
        for (int j = 0; j < 8; j++) acc[i][j] = 0.f;

    for (int k0 = 0; k0 < EE; k0 += 16) {
        __syncthreads();
#pragma unroll
        for (int li = 0; li < 2; li++) {
            int f4 = tid + li * 256;
            int r = f4 >> 2, c = (f4 & 3) << 2;
            float4 av = *(const float4*)(g_mid + (size_t)(row0 + r) * EE + k0 + c);
            As[c + 0][r] = av.x; As[c + 1][r] = av.y;
            As[c + 2][r] = av.z; As[c + 3][r] = av.w;
            int rb = f4 >> 5, cb = (f4 & 31) << 2;
            float4 bv = *(const float4*)(ow + (size_t)(k0 + rb) * DD + col0 + cb);
            *(float4*)&Bs[rb][cb] = bv;
        }
        __syncthreads();
#pragma unroll
        for (int kk = 0; kk < 16; kk++) {
            float a[8], bb[8];
            *(float4*)(a)      = *(const float4*)&As[kk][ty * 8];
            *(float4*)(a + 4)  = *(const float4*)&As[kk][ty * 8 + 4];
            *(float4*)(bb)     = *(const float4*)&Bs[kk][tx * 8];
            *(float4*)(bb + 4) = *(const float4*)&Bs[kk][tx * 8 + 4];
#pragma unroll
            for (int i = 0; i < 8; i++)
#pragma unroll
                for (int j = 0; j < 8; j++) acc[i][j] = fmaf(a[i], bb[j], acc[i][j]);
        }
    }

#pragma unroll
    for (int i = 0; i < 8; i++) {
        int row = row0 + ty * 8 + i;
#pragma unroll
        for (int j = 0; j < 8; j++) {
            int col = col0 + tx * 8 + j;
            size_t idx = (size_t)row * DD + col;
            out[idx] = fmaf(x[idx], res_scale[col], acc[i][j]);
        }
    }
}

// -------------------- launch --------------------
extern "C" void kernel_launch(void* const* d_in, const int* in_sizes, int n_in,
                              void* d_out, int out_size)
{
    const float* x     = (const float*)d_in[0];
    const float* w     = (const float*)d_in[1];
    const float* uvw   = (const float*)d_in[2];
    const float* ow    = (const float*)d_in[3];
    const float* gamma = (const float*)d_in[4];
    const float* beta  = (const float*)d_in[5];
    const float* g     = (const float*)d_in[6];
    const float* res   = (const float*)d_in[7];
    float* out = (float*)d_out;

    rownorm_kernel<<<ROWS / 8, 256>>>(x, g);
    gemm_uv<<<dim3(UVC / 128, ROWS / 128), 256>>>(x, uvw, gamma, beta);
    gemm_qk<<<dim3(NN / 128, NN / 128, NB), 256>>>(w);
    gemm_av<<<dim3(EE / 128, NN / 128, NB), 256>>>();
    gemm_final<<<dim3(DD / 128, ROWS / 128), 256>>>(x, ow, res, out);
}

// round 4
// speedup vs baseline: 2.2642x; 2.2642x over previous
#include <cuda_runtime.h>
#include <cuda_bf16.h>
#include <math.h>
#include <stdint.h>

typedef __nv_bfloat16 bf16;

// Shapes: B=32, N=1024, D=512, E=1024, S=128
#define ROWS 32768
#define DD   512
#define EE   1024
#define SS   128
#define NB   32
#define NN   1024
#define UVC  2176

// -------------------- scratch --------------------
__device__ float g_scale[ROWS];
__device__ float g_u[(size_t)ROWS * EE];
__device__ float g_v[(size_t)ROWS * EE];
__device__ float g_q[(size_t)ROWS * SS];
__device__ float g_k[(size_t)ROWS * SS];
__device__ float g_attn[(size_t)NB * NN * NN];
__device__ float g_mid[(size_t)ROWS * EE];

// -------------------- PTX helpers --------------------
__device__ __forceinline__ uint32_t smem_u32(const void* p) {
    return (uint32_t)__cvta_generic_to_shared(p);
}
__device__ __forceinline__ void ldsm_x4(uint32_t* r, uint32_t addr) {
    asm volatile("ldmatrix.sync.aligned.m8n8.x4.shared.b16 {%0,%1,%2,%3}, [%4];"
        : "=r"(r[0]), "=r"(r[1]), "=r"(r[2]), "=r"(r[3]) : "r"(addr));
}
__device__ __forceinline__ void ldsm_x4_t(uint32_t* r, uint32_t addr) {
    asm volatile("ldmatrix.sync.aligned.m8n8.x4.trans.shared.b16 {%0,%1,%2,%3}, [%4];"
        : "=r"(r[0]), "=r"(r[1]), "=r"(r[2]), "=r"(r[3]) : "r"(addr));
}
__device__ __forceinline__ void mma_bf16(float* d, const uint32_t* a, const uint32_t* b) {
    asm volatile("mma.sync.aligned.m16n8k16.row.col.f32.bf16.bf16.f32 "
        "{%0,%1,%2,%3}, {%4,%5,%6,%7}, {%8,%9}, {%0,%1,%2,%3};"
        : "+f"(d[0]), "+f"(d[1]), "+f"(d[2]), "+f"(d[3])
        : "r"(a[0]), "r"(a[1]), "r"(a[2]), "r"(a[3]), "r"(b[0]), "r"(b[1]));
}
__device__ __forceinline__ uint32_t pk2(bf16 a, bf16 b) {
    return (uint32_t)__bfloat16_as_ushort(a) | ((uint32_t)__bfloat16_as_ushort(b) << 16);
}

// -------------------- row norm --------------------
__global__ __launch_bounds__(256) void rownorm_kernel(const float* __restrict__ x,
                                                      const float* __restrict__ gptr)
{
    int row  = blockIdx.x * 8 + (threadIdx.x >> 5);
    int lane = threadIdx.x & 31;
    const float* xr = x + (size_t)row * DD;
    float s = 0.f;
#pragma unroll
    for (int t = 0; t < 16; t++) {
        float v = xr[lane + 32 * t];
        s = fmaf(v, v, s);
    }
#pragma unroll
    for (int o = 16; o; o >>= 1) s += __shfl_xor_sync(0xffffffffu, s, o);
    if (lane == 0) g_scale[row] = gptr[0] / fmaxf(sqrtf(s), 1e-5f);
}

// ==========================================================================
// Unified tensor-core GEMM via mma.sync m16n8k16 bf16, bf16x3 split.
// 128x128 CTA tile, 8 warps (2x4), warp = 64x32 = 4x4 grid of 16x8 mma.
// MODE 0: uv   = silu((x*scale) @ uv_w), scatter u/v/q/k
// MODE 1: attn = relu((q k^T + bias)/sqrtS)^2            (B is [n][k])
// MODE 2: mid  = u * (attn @ v)
// MODE 3: out  = x*res_scale + mid @ o_w
// ==========================================================================
#define LDA_S   40     // bf16 per A/Bcol smem row: 80 B stride (conflict-free ldsm)
#define LDB_R   136    // bf16 per Brow smem row: 272 B stride (conflict-free ldsm)
#define A_BY    (128 * LDA_S * 2)   // 10240
#define BROW_BY (32 * LDB_R * 2)    // 8704
#define BCOL_BY (128 * LDA_S * 2)   // 10240

template<int MODE>
__global__ __launch_bounds__(256) void gemm_tc(
    const float* __restrict__ Pa,   // MODE0: x
    const float* __restrict__ Pb,   // MODE0: uvw  MODE3: o_w
    const float* __restrict__ e0,   // MODE0: gamma MODE1: w  MODE3: x
    const float* __restrict__ e1,   // MODE0: beta            MODE3: res_scale
    float* __restrict__ outp)       // MODE3: out
{
    constexpr bool BCOL   = (MODE == 1);
    constexpr bool SCALEA = (MODE == 0);
    constexpr int  K      = (MODE == 0) ? DD : (MODE == 1) ? SS : (MODE == 2) ? NN : EE;

    extern __shared__ char smem[];
    bf16* sAhi = (bf16*)smem;
    bf16* sAlo = (bf16*)(smem + A_BY);
    bf16* sBhi = (bf16*)(smem + 2 * A_BY);
    constexpr int bby = BCOL ? BCOL_BY : BROW_BY;
    bf16* sBlo = (bf16*)(smem + 2 * A_BY + bby);
    __shared__ float sS[128];

    const int b    = blockIdx.z;
    const int row0 = blockIdx.y * 128;
    const int col0 = blockIdx.x * 128;
    const int tid  = threadIdx.x, wid = tid >> 5, lane = tid & 31;
    const int warp_m = wid >> 2, warp_n = wid & 3;   // 2 x 4

    const float* A;
    const float* B;
    int lda, ldb;
    if (MODE == 0) { A = Pa;                               lda = DD;
                     B = Pb;                               ldb = UVC; }
    if (MODE == 1) { A = g_q    + (size_t)b * NN * SS;     lda = SS;
                     B = g_k    + (size_t)b * NN * SS;     ldb = SS;  }
    if (MODE == 2) { A = g_attn + (size_t)b * NN * NN;     lda = NN;
                     B = g_v    + (size_t)b * NN * EE;     ldb = EE;  }
    if (MODE == 3) { A = g_mid;                            lda = EE;
                     B = Pb;                               ldb = DD;  }

    if (SCALEA && tid < 128) sS[tid] = g_scale[row0 + tid];

    const uint32_t uAhi = smem_u32(sAhi), uAlo = smem_u32(sAlo);
    const uint32_t uBhi = smem_u32(sBhi), uBlo = smem_u32(sBlo);

    float acc[4][4][4];
#pragma unroll
    for (int i = 0; i < 4; i++)
#pragma unroll
        for (int j = 0; j < 4; j++)
#pragma unroll
            for (int e = 0; e < 4; e++) acc[i][j][e] = 0.f;

    for (int k0 = 0; k0 < K; k0 += 32) {
        __syncthreads();
        // ---- A tile: 128 rows x 32 k, fp32 -> hi/lo bf16 ----
#pragma unroll
        for (int i = 0; i < 4; i++) {
            int id = tid + 256 * i;
            int r = id >> 3, cw = (id & 7) << 2;
            float4 av = *(const float4*)(A + (size_t)(row0 + r) * lda + k0 + cw);
            float sc = SCALEA ? sS[r] : 1.f;
            float f[4] = {av.x * sc, av.y * sc, av.z * sc, av.w * sc};
            bf16 h[4], l[4];
#pragma unroll
            for (int j = 0; j < 4; j++) {
                h[j] = __float2bfloat16(f[j]);
                l[j] = __float2bfloat16(f[j] - __bfloat162float(h[j]));
            }
            *(uint2*)&sAhi[r * LDA_S + cw] = make_uint2(pk2(h[0], h[1]), pk2(h[2], h[3]));
            *(uint2*)&sAlo[r * LDA_S + cw] = make_uint2(pk2(l[0], l[1]), pk2(l[2], l[3]));
        }
        // ---- B tile ----
        if (BCOL) {     // [n][k]: 128 n-rows x 32 k
#pragma unroll
            for (int i = 0; i < 4; i++) {
                int id = tid + 256 * i;
                int r = id >> 3, cw = (id & 7) << 2;
                float4 bv = *(const float4*)(B + (size_t)(col0 + r) * ldb + k0 + cw);
                float f[4] = {bv.x, bv.y, bv.z, bv.w};
                bf16 h[4], l[4];
#pragma unroll
                for (int j = 0; j < 4; j++) {
                    h[j] = __float2bfloat16(f[j]);
                    l[j] = __float2bfloat16(f[j] - __bfloat162float(h[j]));
                }
                *(uint2*)&sBhi[r * LDA_S + cw] = make_uint2(pk2(h[0], h[1]), pk2(h[2], h[3]));
                *(uint2*)&sBlo[r * LDA_S + cw] = make_uint2(pk2(l[0], l[1]), pk2(l[2], l[3]));
            }
        } else {        // [k][n]: 32 k-rows x 128 n
#pragma unroll
            for (int i = 0; i < 4; i++) {
                int id = tid + 256 * i;
                int r = id >> 5, cw = (id & 31) << 2;
                float4 bv = *(const float4*)(B + (size_t)(k0 + r) * ldb + col0 + cw);
                float f[4] = {bv.x, bv.y, bv.z, bv.w};
                bf16 h[4], l[4];
#pragma unroll
                for (int j = 0; j < 4; j++) {
                    h[j] = __float2bfloat16(f[j]);
                    l[j] = __float2bfloat16(f[j] - __bfloat162float(h[j]));
                }
                *(uint2*)&sBhi[r * LDB_R + cw] = make_uint2(pk2(h[0], h[1]), pk2(h[2], h[3]));
                *(uint2*)&sBlo[r * LDB_R + cw] = make_uint2(pk2(l[0], l[1]), pk2(l[2], l[3]));
            }
        }
        __syncthreads();

        // ---- compute: 2 k-steps of 16 ----
#pragma unroll
        for (int ks = 0; ks < 32; ks += 16) {
            // A fragments: 4 m-tiles of 16x16 (hi + lo)
            uint32_t ahi[4][4], alo[4][4];
#pragma unroll
            for (int mt = 0; mt < 4; mt++) {
                int m = warp_m * 64 + mt * 16 + (lane & 15);
                uint32_t off = (uint32_t)(m * LDA_S + ks + ((lane >> 4) << 3)) * 2;
                ldsm_x4(ahi[mt], uAhi + off);
                ldsm_x4(alo[mt], uAlo + off);
            }
            // B fragments: 4 n-subtiles of 8 (hi + lo)
            uint32_t bhi[4][2], blo[4][2];
            if (BCOL) {
#pragma unroll
                for (int p = 0; p < 2; p++) {
                    int n = warp_n * 32 + p * 16 + (lane & 7) + ((lane >> 4) << 3);
                    uint32_t off = (uint32_t)(n * LDA_S + ks + (((lane >> 3) & 1) << 3)) * 2;
                    uint32_t r4[4];
                    ldsm_x4(r4, uBhi + off);
                    bhi[2*p][0] = r4[0]; bhi[2*p][1] = r4[1];
                    bhi[2*p+1][0] = r4[2]; bhi[2*p+1][1] = r4[3];
                    ldsm_x4(r4, uBlo + off);
                    blo[2*p][0] = r4[0]; blo[2*p][1] = r4[1];
                    blo[2*p+1][0] = r4[2]; blo[2*p+1][1] = r4[3];
                }
            } else {
#pragma unroll
                for (int p = 0; p < 2; p++) {
                    int kk = ks + (((lane >> 3) & 1) << 3) + (lane & 7);
                    int n  = warp_n * 32 + p * 16 + ((lane >> 4) << 3);
                    uint32_t off = (uint32_t)(kk * LDB_R + n) * 2;
                    uint32_t r4[4];
                    ldsm_x4_t(r4, uBhi + off);
                    bhi[2*p][0] = r4[0]; bhi[2*p][1] = r4[1];
                    bhi[2*p+1][0] = r4[2]; bhi[2*p+1][1] = r4[3];
                    ldsm_x4_t(r4, uBlo + off);
                    blo[2*p][0] = r4[0]; blo[2*p][1] = r4[1];
                    blo[2*p+1][0] = r4[2]; blo[2*p+1][1] = r4[3];
                }
            }
            // 3-term bf16x3 MMAs
#pragma unroll
            for (int mt = 0; mt < 4; mt++) {
#pragma unroll
                for (int nt = 0; nt < 4; nt++) {
                    mma_bf16(acc[mt][nt], ahi[mt], bhi[nt]);
                    mma_bf16(acc[mt][nt], ahi[mt], blo[nt]);
                    mma_bf16(acc[mt][nt], alo[mt], bhi[nt]);
                }
            }
        }
    }

    // -------------------- epilogue (direct from accumulators) --------------------
    const float inv_sqrt_s = 0.088388347648318447f;   // 1/sqrt(128)
#pragma unroll
    for (int mt = 0; mt < 4; mt++) {
#pragma unroll
        for (int nt = 0; nt < 4; nt++) {
            int mb = row0 + warp_m * 64 + mt * 16 + (lane >> 2);
            int nb = col0 + warp_n * 32 + nt * 8 + ((lane & 3) << 1);
#pragma unroll
            for (int e = 0; e < 4; e++) {
                int m = mb + ((e >> 1) << 3);   // +8 for e=2,3
                int n = nb + (e & 1);
                float val = acc[mt][nt][e];
                if (MODE == 0) {
                    float sv = val / (1.f + __expf(-val));
                    if (n < EE) {
                        g_u[(size_t)m * EE + n] = sv;
                    } else if (n < 2 * EE) {
                        g_v[(size_t)m * EE + (n - EE)] = sv;
                    } else {
                        int s = n - 2 * EE;
                        g_q[(size_t)m * SS + s] = fmaf(sv, e0[s],      e1[s]);
                        g_k[(size_t)m * SS + s] = fmaf(sv, e0[SS + s], e1[SS + s]);
                    }
                } else if (MODE == 1) {
                    float t = (val + e0[NN - 1 + n - m]) * inv_sqrt_s;
                    t = fmaxf(t, 0.f);
                    g_attn[((size_t)b * NN + m) * NN + n] = t * t;
                } else if (MODE == 2) {
                    size_t idx = ((size_t)b * NN + m) * EE + n;
                    g_mid[idx] = g_u[idx] * val;
                } else {
                    size_t idx = (size_t)m * DD + n;
                    outp[idx] = fmaf(e0[idx], e1[n], val);
                }
            }
        }
    }
}

// -------------------- launch --------------------
extern "C" void kernel_launch(void* const* d_in, const int* in_sizes, int n_in,
                              void* d_out, int out_size)
{
    const float* x     = (const float*)d_in[0];
    const float* w     = (const float*)d_in[1];
    const float* uvw   = (const float*)d_in[2];
    const float* ow    = (const float*)d_in[3];
    const float* gamma = (const float*)d_in[4];
    const float* beta  = (const float*)d_in[5];
    const float* g     = (const float*)d_in[6];
    const float* res   = (const float*)d_in[7];
    float* out = (float*)d_out;

    const size_t smem_row = 2 * A_BY + 2 * BROW_BY;  // 37888
    const size_t smem_col = 2 * A_BY + 2 * BCOL_BY;  // 40960

    rownorm_kernel<<<ROWS / 8, 256>>>(x, g);

    // uv = silu((x*scale) @ uv_w), scatter u/v/q/k
    gemm_tc<0><<<dim3(UVC / 128, ROWS / 128, 1), 256, smem_row>>>(
        x, uvw, gamma, beta, nullptr);

    // attn = relu((q k^T + bias)/sqrtS)^2   (batched)
    gemm_tc<1><<<dim3(NN / 128, NN / 128, NB), 256, smem_col>>>(
        nullptr, nullptr, w, nullptr, nullptr);

    // mid = u * (attn @ v)   (batched)
    gemm_tc<2><<<dim3(EE / 128, NN / 128, NB), 256, smem_row>>>(
        nullptr, nullptr, nullptr, nullptr, nullptr);

    // out = x*res_scale + mid @ o_w
    gemm_tc<3><<<dim3(DD / 128, ROWS / 128, 1), 256, smem_row>>>(
        nullptr, ow, x, res, out);
}

// round 6
// speedup vs baseline: 2.5172x; 1.1117x over previous
#include <cuda_runtime.h>
#include <cuda_bf16.h>
#include <math.h>
#include <stdint.h>

typedef __nv_bfloat16 bf16;

// Shapes: B=32, N=1024, D=512, E=1024, S=128
#define ROWS 32768
#define DD   512
#define EE   1024
#define SS   128
#define NB   32
#define NN   1024
#define UVC  2176

// -------------------- scratch: pre-split bf16 planes --------------------
__device__ bf16 g_xs_h[(size_t)ROWS * DD];
__device__ bf16 g_xs_l[(size_t)ROWS * DD];
__device__ bf16 g_uvwt_h[(size_t)UVC * DD];    // uv_w^T  [2176][512]
__device__ bf16 g_uvwt_l[(size_t)UVC * DD];
__device__ bf16 g_owt_h[(size_t)DD * EE];      // o_w^T   [512][1024]
__device__ bf16 g_owt_l[(size_t)DD * EE];
__device__ float g_u[(size_t)ROWS * EE];
__device__ bf16 g_q_h[(size_t)ROWS * SS];
__device__ bf16 g_q_l[(size_t)ROWS * SS];
__device__ bf16 g_k_h[(size_t)ROWS * SS];
__device__ bf16 g_k_l[(size_t)ROWS * SS];
__device__ bf16 g_attn_h[(size_t)NB * NN * NN];
__device__ bf16 g_attn_l[(size_t)NB * NN * NN];
__device__ bf16 g_vt_h[(size_t)NB * EE * NN];  // v^T [b][e][n]
__device__ bf16 g_vt_l[(size_t)NB * EE * NN];
__device__ bf16 g_mid_h[(size_t)ROWS * EE];
__device__ bf16 g_mid_l[(size_t)ROWS * EE];

// -------------------- PTX helpers --------------------
__device__ __forceinline__ uint32_t smem_u32(const void* p) {
    return (uint32_t)__cvta_generic_to_shared(p);
}
__device__ __forceinline__ void ldsm_x4(uint32_t* r, uint32_t addr) {
    asm volatile("ldmatrix.sync.aligned.m8n8.x4.shared.b16 {%0,%1,%2,%3}, [%4];"
        : "=r"(r[0]), "=r"(r[1]), "=r"(r[2]), "=r"(r[3]) : "r"(addr));
}
__device__ __forceinline__ void mma_bf16(float* d, const uint32_t* a, const uint32_t* b) {
    asm volatile("mma.sync.aligned.m16n8k16.row.col.f32.bf16.bf16.f32 "
        "{%0,%1,%2,%3}, {%4,%5,%6,%7}, {%8,%9}, {%0,%1,%2,%3};"
        : "+f"(d[0]), "+f"(d[1]), "+f"(d[2]), "+f"(d[3])
        : "r"(a[0]), "r"(a[1]), "r"(a[2]), "r"(a[3]), "r"(b[0]), "r"(b[1]));
}
#define CP16(d, s)  asm volatile("cp.async.cg.shared.global [%0], [%1], 16;" :: "r"(d), "l"(s))
#define CP_COMMIT() asm volatile("cp.async.commit_group;" ::: "memory")
#define CP_WAIT(n)  asm volatile("cp.async.wait_group %0;" :: "n"(n) : "memory")

__device__ __forceinline__ uint32_t pk2(bf16 a, bf16 b) {
    return (uint32_t)__bfloat16_as_ushort(a) | ((uint32_t)__bfloat16_as_ushort(b) << 16);
}
__device__ __forceinline__ void split2(float f, bf16& h, bf16& l) {
    h = __float2bfloat16(f);
    l = __float2bfloat16(f - __bfloat162float(h));
}
__device__ __forceinline__ uint32_t pksplit(float a, float b, uint32_t& lo) {
    bf16 h0, l0, h1, l1;
    split2(a, h0, l0); split2(b, h1, l1);
    lo = pk2(l0, l1);
    return pk2(h0, h1);
}

// -------------------- prep kernels --------------------
__global__ __launch_bounds__(256) void rownorm_split(const float* __restrict__ x,
                                                     const float* __restrict__ gptr)
{
    int row  = blockIdx.x * 8 + (threadIdx.x >> 5);
    int lane = threadIdx.x & 31;
    const float* xr = x + (size_t)row * DD;
    float vbuf[16];
    float s = 0.f;
#pragma unroll
    for (int t = 0; t < 16; t++) {
        vbuf[t] = xr[lane + 32 * t];
        s = fmaf(vbuf[t], vbuf[t], s);
    }
#pragma unroll
    for (int o = 16; o; o >>= 1) s += __shfl_xor_sync(0xffffffffu, s, o);
    float sc = gptr[0] / fmaxf(sqrtf(s), 1e-5f);
#pragma unroll
    for (int t = 0; t < 16; t++) {
        bf16 h, l; split2(vbuf[t] * sc, h, l);
        size_t idx = (size_t)row * DD + lane + 32 * t;
        g_xs_h[idx] = h;
        g_xs_l[idx] = l;
    }
}
// W=0: uvwt[c][r] = split(uv_w[r][c])  (src [512][2176])
// W=1: owt[d][e]  = split(o_w[e][d])   (src [1024][512])
template<int W>
__global__ __launch_bounds__(256) void wsplit(const float* __restrict__ src)
{
    int id = blockIdx.x * 256 + threadIdx.x;
    if (W == 0) {
        if (id >= UVC * DD) return;
        int c = id / DD, r = id % DD;
        bf16 h, l; split2(src[(size_t)r * UVC + c], h, l);
        g_uvwt_h[id] = h; g_uvwt_l[id] = l;
    } else {
        if (id >= DD * EE) return;
        int e = id % EE, d = id / EE;
        bf16 h, l; split2(src[(size_t)e * DD + d], h, l);
        g_owt_h[id] = h; g_owt_l[id] = l;
    }
}

// ==========================================================================
// mma.sync bf16x3 GEMM, pre-split operands, cp.async double buffered.
// 128x128 CTA tile, BK=32, 8 warps (2x4), warp 64x32 = 4x4 m16n8k16 grid.
// All operands K-major [rows][K] (B = [n][k]).
// MODE 0: uv (A=xs, B=uvwt, K=512)   epi: silu -> u / vt(staged) / q,k
// MODE 1: qk (A=q,  B=k,    K=128)   epi: +bias, relu^2/sqrtS -> attn
// MODE 2: av (A=attn, B=vt, K=1024)  epi: u-gate -> mid
// MODE 3: fin(A=mid,  B=owt,K=1024)  epi: residual -> out
// ==========================================================================
#define LDA      40                      // elems per smem row (80 B, conflict-free)
#define PLANE_BY (128 * LDA * 2)         // 10240
#define BUF_BY   (4 * PLANE_BY)          // 40960
#define SMEM_SZ  (2 * BUF_BY)            // 81920

template<int MODE>
__global__ __launch_bounds__(256, 2) void gemm6(
    const float* __restrict__ e0, const float* __restrict__ e1, float* __restrict__ outp)
{
    constexpr int K      = (MODE == 0) ? DD : (MODE == 1) ? SS : NN;
    constexpr int CHUNKS = K / 32;

    extern __shared__ char smem[];
    const uint32_t sbase = smem_u32(smem);
    const int tid = threadIdx.x, wid = tid >> 5, lane = tid & 31;
    const int warp_m = wid >> 2, warp_n = wid & 3;
    const int bx = blockIdx.x, b = blockIdx.z;
    const int row0 = blockIdx.y * 128, col0 = bx * 128;

    const bf16 *planes[4];
    if (MODE == 0) { planes[0] = g_xs_h;   planes[1] = g_xs_l;
                     planes[2] = g_uvwt_h; planes[3] = g_uvwt_l; }
    if (MODE == 1) { planes[0] = g_q_h + (size_t)b * NN * SS;  planes[1] = g_q_l + (size_t)b * NN * SS;
                     planes[2] = g_k_h + (size_t)b * NN * SS;  planes[3] = g_k_l + (size_t)b * NN * SS; }
    if (MODE == 2) { planes[0] = g_attn_h + (size_t)b * NN * NN; planes[1] = g_attn_l + (size_t)b * NN * NN;
                     planes[2] = g_vt_h + (size_t)b * EE * NN;   planes[3] = g_vt_l + (size_t)b * EE * NN; }
    if (MODE == 3) { planes[0] = g_mid_h;  planes[1] = g_mid_l;
                     planes[2] = g_owt_h;  planes[3] = g_owt_l; }

    // per-thread load coords: 512 16B-units per plane, 2 per thread
    const int lr0 = tid >> 2, lc0 = tid & 3;           // rows 0..63
    const int lr1 = lr0 + 64;

    float acc[4][4][4];
#pragma unroll
    for (int i = 0; i < 4; i++)
#pragma unroll
        for (int j = 0; j < 4; j++)
#pragma unroll
            for (int e = 0; e < 4; e++) acc[i][j][e] = 0.f;

    auto load_chunk = [&](int c, int buf) {
        const uint32_t bo = sbase + buf * BUF_BY;
        const int k0 = c * 32;
#pragma unroll
        for (int p = 0; p < 4; p++) {
            const bf16* src = planes[p] + k0;
            const int rbase = (p < 2) ? row0 : col0;
            CP16(bo + p * PLANE_BY + lr0 * 80 + lc0 * 16,
                 src + (size_t)(rbase + lr0) * K + lc0 * 8);
            CP16(bo + p * PLANE_BY + lr1 * 80 + lc0 * 16,
                 src + (size_t)(rbase + lr1) * K + lc0 * 8);
        }
        CP_COMMIT();
    };

    load_chunk(0, 0);

    for (int c = 0; c < CHUNKS; c++) {
        if (c + 1 < CHUNKS) { load_chunk(c + 1, (c + 1) & 1); CP_WAIT(1); }
        else                { CP_WAIT(0); }
        __syncthreads();

        const uint32_t bo = sbase + (c & 1) * BUF_BY;
        const uint32_t uAh = bo, uAl = bo + PLANE_BY;
        const uint32_t uBh = bo + 2 * PLANE_BY, uBl = bo + 3 * PLANE_BY;

#pragma unroll
        for (int ks = 0; ks < 32; ks += 16) {
            // B fragments: 2 groups of 16 n (4 n8 tiles), hi+lo
            uint32_t bhi[4][2], blo[4][2];
#pragma unroll
            for (int p = 0; p < 2; p++) {
                int n = warp_n * 32 + p * 16 + (lane & 7) + ((lane >> 4) << 3);
                uint32_t off = (uint32_t)(n * LDA + ks + (((lane >> 3) & 1) << 3)) * 2;
                uint32_t r4[4];
                ldsm_x4(r4, uBh + off);
                bhi[2*p][0] = r4[0]; bhi[2*p][1] = r4[1];
                bhi[2*p+1][0] = r4[2]; bhi[2*p+1][1] = r4[3];
                ldsm_x4(r4, uBl + off);
                blo[2*p][0] = r4[0]; blo[2*p][1] = r4[1];
                blo[2*p+1][0] = r4[2]; blo[2*p+1][1] = r4[3];
            }
            // A fragments per mt, 12 MMAs each
#pragma unroll
            for (int mt = 0; mt < 4; mt++) {
                int m = warp_m * 64 + mt * 16 + (lane & 15);
                uint32_t off = (uint32_t)(m * LDA + ks + ((lane >> 4) << 3)) * 2;
                uint32_t ahi[4], alo[4];
                ldsm_x4(ahi, uAh + off);
                ldsm_x4(alo, uAl + off);
#pragma unroll
                for (int nt = 0; nt < 4; nt++) {
                    mma_bf16(acc[mt][nt], ahi, bhi[nt]);
                    mma_bf16(acc[mt][nt], ahi, blo[nt]);
                    mma_bf16(acc[mt][nt], alo, bhi[nt]);
                }
            }
        }
        __syncthreads();
    }

    // -------------------- epilogue --------------------
    const float inv_sqrt_s = 0.088388347648318447f;   // 1/sqrt(128)
    bf16* stH = (bf16*)smem;                          // v-transpose staging (aliased)
    bf16* stL = (bf16*)(smem + 128 * 136 * 2);

#pragma unroll
    for (int mt = 0; mt < 4; mt++) {
#pragma unroll
        for (int nt = 0; nt < 4; nt++) {
            int mb = row0 + warp_m * 64 + mt * 16 + (lane >> 2);
            int nb = col0 + warp_n * 32 + nt * 8 + ((lane & 3) << 1);
#pragma unroll
            for (int h = 0; h < 2; h++) {
                int m = mb + 8 * h;
                int n = nb;
                float v0 = acc[mt][nt][h * 2 + 0];
                float v1 = acc[mt][nt][h * 2 + 1];
                if (MODE == 0) {
                    float s0 = v0 / (1.f + __expf(-v0));
                    float s1 = v1 / (1.f + __expf(-v1));
                    if (bx < 8) {                      // u (fp32)
                        *(float2*)(g_u + (size_t)m * EE + n) = make_float2(s0, s1);
                    } else if (bx < 16) {              // v -> stage transposed split
                        bf16 h0, l0, h1, l1;
                        split2(s0, h0, l0); split2(s1, h1, l1);
                        int nl = n - col0, ml = m - row0;
                        stH[nl * 136 + ml] = h0;       stL[nl * 136 + ml] = l0;
                        stH[(nl + 1) * 136 + ml] = h1; stL[(nl + 1) * 136 + ml] = l1;
                    } else {                           // q,k split
                        int s = n - 2 * EE;
                        uint32_t lo, hi;
                        size_t o = (size_t)m * SS + s;
                        hi = pksplit(fmaf(s0, e0[s], e1[s]), fmaf(s1, e0[s + 1], e1[s + 1]), lo);
                        *(uint32_t*)(g_q_h + o) = hi; *(uint32_t*)(g_q_l + o) = lo;
                        hi = pksplit(fmaf(s0, e0[SS + s], e1[SS + s]),
                                     fmaf(s1, e0[SS + s + 1], e1[SS + s + 1]), lo);
                        *(uint32_t*)(g_k_h + o) = hi; *(uint32_t*)(g_k_l + o) = lo;
                    }
                } else if (MODE == 1) {
                    float t0 = (v0 + e0[NN - 1 + n - m]) * inv_sqrt_s;     t0 = fmaxf(t0, 0.f);
                    float t1 = (v1 + e0[NN - 1 + n + 1 - m]) * inv_sqrt_s; t1 = fmaxf(t1, 0.f);
                    uint32_t lo, hi = pksplit(t0 * t0, t1 * t1, lo);
                    size_t o = ((size_t)b * NN + m) * NN + n;
                    *(uint32_t*)(g_attn_h + o) = hi;
                    *(uint32_t*)(g_attn_l + o) = lo;
                } else if (MODE == 2) {
                    size_t o = ((size_t)b * NN + m) * EE + n;
                    float2 uu = *(const float2*)(g_u + o);
                    uint32_t lo, hi = pksplit(uu.x * v0, uu.y * v1, lo);
                    *(uint32_t*)(g_mid_h + o) = hi;
                    *(uint32_t*)(g_mid_l + o) = lo;
                } else {
                    size_t o = (size_t)m * DD + n;
                    float2 xv = *(const float2*)(e0 + o);
                    *(float2*)(outp + o) = make_float2(fmaf(xv.x, e1[n], v0),
                                                       fmaf(xv.y, e1[n + 1], v1));
                }
            }
        }
    }

    // v-block: coalesced copy-out of staged transposed tile
    if (MODE == 0 && bx >= 8 && bx < 16) {
        __syncthreads();
        const int bb = row0 >> 10, mloc = row0 & (NN - 1);
        const int ebase = col0 - EE;
#pragma unroll
        for (int it = 0; it < 8; it++) {
            int id = tid + 256 * it;
            int el = id >> 4, mw = id & 15;
            size_t o = ((size_t)bb * EE + ebase + el) * NN + mloc + mw * 8;
            *(uint4*)(g_vt_h + o) = *(const uint4*)&stH[el * 136 + mw * 8];
            *(uint4*)(g_vt_l + o) = *(const uint4*)&stL[el * 136 + mw * 8];
        }
    }
}

// -------------------- launch --------------------
extern "C" void kernel_launch(void* const* d_in, const int* in_sizes, int n_in,
                              void* d_out, int out_size)
{
    const float* x     = (const float*)d_in[0];
    const float* w     = (const float*)d_in[1];
    const float* uvw   = (const float*)d_in[2];
    const float* ow    = (const float*)d_in[3];
    const float* gamma = (const float*)d_in[4];
    const float* beta  = (const float*)d_in[5];
    const float* g     = (const float*)d_in[6];
    const float* res   = (const float*)d_in[7];
    float* out = (float*)d_out;

    cudaFuncSetAttribute(gemm6<0>, cudaFuncAttributeMaxDynamicSharedMemorySize, SMEM_SZ);
    cudaFuncSetAttribute(gemm6<1>, cudaFuncAttributeMaxDynamicSharedMemorySize, SMEM_SZ);
    cudaFuncSetAttribute(gemm6<2>, cudaFuncAttributeMaxDynamicSharedMemorySize, SMEM_SZ);
    cudaFuncSetAttribute(gemm6<3>, cudaFuncAttributeMaxDynamicSharedMemorySize, SMEM_SZ);

    rownorm_split<<<ROWS / 8, 256>>>(x, g);
    wsplit<0><<<(UVC * DD + 255) / 256, 256>>>(uvw);
    wsplit<1><<<(DD * EE + 255) / 256, 256>>>(ow);

    gemm6<0><<<dim3(UVC / 128, ROWS / 128, 1), 256, SMEM_SZ>>>(gamma, beta, nullptr);
    gemm6<1><<<dim3(NN / 128, NN / 128, NB),   256, SMEM_SZ>>>(w, nullptr, nullptr);
    gemm6<2><<<dim3(EE / 128, NN / 128, NB),   256, SMEM_SZ>>>(nullptr, nullptr, nullptr);
    gemm6<3><<<dim3(DD / 128, ROWS / 128, 1),  256, SMEM_SZ>>>(x, res, out);
}

// round 9
// speedup vs baseline: 2.5718x; 1.0217x over previous
#include <cuda_runtime.h>
#include <cuda_bf16.h>
#include <math.h>
#include <stdint.h>

typedef __nv_bfloat16 bf16;

// Shapes: B=32, N=1024, D=512, E=1024, S=128
#define ROWS 32768
#define DD   512
#define EE   1024
#define SS   128
#define NB   32
#define NN   1024
#define UVC  2176

// -------------------- scratch: pre-split bf16 planes --------------------
__device__ bf16 g_xs_h[(size_t)ROWS * DD];
__device__ bf16 g_xs_l[(size_t)ROWS * DD];
__device__ bf16 g_uvwt_h[(size_t)UVC * DD];    // uv_w^T  [2176][512]
__device__ bf16 g_uvwt_l[(size_t)UVC * DD];
__device__ bf16 g_owt_h[(size_t)DD * EE];      // o_w^T   [512][1024]
__device__ bf16 g_owt_l[(size_t)DD * EE];
__device__ float g_u[(size_t)ROWS * EE];
__device__ bf16 g_q_h[(size_t)ROWS * SS];
__device__ bf16 g_q_l[(size_t)ROWS * SS];
__device__ bf16 g_k_h[(size_t)ROWS * SS];
__device__ bf16 g_k_l[(size_t)ROWS * SS];
__device__ bf16 g_attn_h[(size_t)NB * NN * NN];
__device__ bf16 g_attn_l[(size_t)NB * NN * NN];
__device__ bf16 g_vt_h[(size_t)NB * EE * NN];  // v^T [b][e][n]
__device__ bf16 g_vt_l[(size_t)NB * EE * NN];
__device__ bf16 g_mid_h[(size_t)ROWS * EE];
__device__ bf16 g_mid_l[(size_t)ROWS * EE];

// -------------------- PTX helpers --------------------
__device__ __forceinline__ uint32_t smem_u32(const void* p) {
    return (uint32_t)__cvta_generic_to_shared(p);
}
__device__ __forceinline__ void ldsm_x4(uint32_t* r, uint32_t addr) {
    asm volatile("ldmatrix.sync.aligned.m8n8.x4.shared.b16 {%0,%1,%2,%3}, [%4];"
        : "=r"(r[0]), "=r"(r[1]), "=r"(r[2]), "=r"(r[3]) : "r"(addr));
}
__device__ __forceinline__ void mma_bf16(float* d, const uint32_t* a, const uint32_t* b) {
    asm volatile("mma.sync.aligned.m16n8k16.row.col.f32.bf16.bf16.f32 "
        "{%0,%1,%2,%3}, {%4,%5,%6,%7}, {%8,%9}, {%0,%1,%2,%3};"
        : "+f"(d[0]), "+f"(d[1]), "+f"(d[2]), "+f"(d[3])
        : "r"(a[0]), "r"(a[1]), "r"(a[2]), "r"(a[3]), "r"(b[0]), "r"(b[1]));
}
#define CP16(d, s)  asm volatile("cp.async.cg.shared.global [%0], [%1], 16;" :: "r"(d), "l"(s))
#define CP_COMMIT() asm volatile("cp.async.commit_group;" ::: "memory")
#define CP_WAIT(n)  asm volatile("cp.async.wait_group %0;" :: "n"(n) : "memory")

__device__ __forceinline__ uint32_t pk2(bf16 a, bf16 b) {
    return (uint32_t)__bfloat16_as_ushort(a) | ((uint32_t)__bfloat16_as_ushort(b) << 16);
}
__device__ __forceinline__ void split2(float f, bf16& h, bf16& l) {
    h = __float2bfloat16(f);
    l = __float2bfloat16(f - __bfloat162float(h));
}
__device__ __forceinline__ uint32_t pksplit(float a, float b, uint32_t& lo) {
    bf16 h0, l0, h1, l1;
    split2(a, h0, l0); split2(b, h1, l1);
    lo = pk2(l0, l1);
    return pk2(h0, h1);
}

// -------------------- prep kernels --------------------
__global__ __launch_bounds__(256) void rownorm_split(const float* __restrict__ x,
                                                     const float* __restrict__ gptr)
{
    int row  = blockIdx.x * 8 + (threadIdx.x >> 5);
    int lane = threadIdx.x & 31;
    const float* xr = x + (size_t)row * DD;
    float vbuf[16];
    float s = 0.f;
#pragma unroll
    for (int t = 0; t < 16; t++) {
        vbuf[t] = xr[lane + 32 * t];
        s = fmaf(vbuf[t], vbuf[t], s);
    }
#pragma unroll
    for (int o = 16; o; o >>= 1) s += __shfl_xor_sync(0xffffffffu, s, o);
    float sc = gptr[0] / fmaxf(sqrtf(s), 1e-5f);
#pragma unroll
    for (int t = 0; t < 16; t++) {
        bf16 h, l; split2(vbuf[t] * sc, h, l);
        size_t idx = (size_t)row * DD + lane + 32 * t;
        g_xs_h[idx] = h;
        g_xs_l[idx] = l;
    }
}
template<int W>
__global__ __launch_bounds__(256) void wsplit(const float* __restrict__ src)
{
    int id = blockIdx.x * 256 + threadIdx.x;
    if (W == 0) {
        if (id >= UVC * DD) return;
        int c = id / DD, r = id % DD;
        bf16 h, l; split2(src[(size_t)r * UVC + c], h, l);
        g_uvwt_h[id] = h; g_uvwt_l[id] = l;
    } else {
        if (id >= DD * EE) return;
        int e = id % EE, d = id / EE;
        bf16 h, l; split2(src[(size_t)e * DD + d], h, l);
        g_owt_h[id] = h; g_owt_l[id] = l;
    }
}

// ==========================================================================
// mma.sync bf16x3 GEMM, pre-split operands, cp.async double-buffered with
// ONE __syncthreads per chunk (loads for c+1 issued right after the barrier,
// overlapping compute of chunk c; overwrite safety proven by the barrier).
// 128x128 CTA tile, BK=32, 8 warps (2x4), warp 64x32 = 4x4 m16n8k16 grid.
// MODE 0: uv (A=xs, B=uvwt, K=512)   epi: silu -> u / vt(staged) / q,k
// MODE 1: qk (A=q,  B=k,    K=128)   epi: +bias, relu^2/sqrtS -> attn
// MODE 2: av (A=attn, B=vt, K=1024)  epi: u-gate -> mid
// MODE 3: fin(A=mid,  B=owt,K=1024)  epi: residual -> out
// ==========================================================================
#define LDA      40                      // elems per smem row (80 B, conflict-free)
#define PLANE_BY (128 * LDA * 2)         // 10240
#define BUF_BY   (4 * PLANE_BY)          // 40960
#define SMEM_SZ  (2 * BUF_BY)            // 81920

template<int MODE>
__global__ __launch_bounds__(256, 2) void gemm9(
    const float* __restrict__ e0, const float* __restrict__ e1, float* __restrict__ outp)
{
    constexpr int K      = (MODE == 0) ? DD : (MODE == 1) ? SS : NN;
    constexpr int CHUNKS = K / 32;

    extern __shared__ char smem[];
    const uint32_t sbase = smem_u32(smem);
    const int tid = threadIdx.x, wid = tid >> 5, lane = tid & 31;
    const int warp_m = wid >> 2, warp_n = wid & 3;
    const int bx = blockIdx.x, b = blockIdx.z;
    const int row0 = blockIdx.y * 128, col0 = bx * 128;

    const bf16 *planes[4];
    if (MODE == 0) { planes[0] = g_xs_h;   planes[1] = g_xs_l;
                     planes[2] = g_uvwt_h; planes[3] = g_uvwt_l; }
    if (MODE == 1) { planes[0] = g_q_h + (size_t)b * NN * SS;  planes[1] = g_q_l + (size_t)b * NN * SS;
                     planes[2] = g_k_h + (size_t)b * NN * SS;  planes[3] = g_k_l + (size_t)b * NN * SS; }
    if (MODE == 2) { planes[0] = g_attn_h + (size_t)b * NN * NN; planes[1] = g_attn_l + (size_t)b * NN * NN;
                     planes[2] = g_vt_h + (size_t)b * EE * NN;   planes[3] = g_vt_l + (size_t)b * EE * NN; }
    if (MODE == 3) { planes[0] = g_mid_h;  planes[1] = g_mid_l;
                     planes[2] = g_owt_h;  planes[3] = g_owt_l; }

    // per-thread load coords: 2 x 16B per plane
    const int lr0 = tid >> 2, lc0 = tid & 3;
    const int lr1 = lr0 + 64;

    float acc[4][4][4];
#pragma unroll
    for (int i = 0; i < 4; i++)
#pragma unroll
        for (int j = 0; j < 4; j++)
#pragma unroll
            for (int e = 0; e < 4; e++) acc[i][j][e] = 0.f;

    auto load_chunk = [&](int c, int buf) {
        const uint32_t bo = sbase + buf * BUF_BY;
        const int k0 = c * 32;
#pragma unroll
        for (int p = 0; p < 4; p++) {
            const bf16* src = planes[p] + k0;
            const int rbase = (p < 2) ? row0 : col0;
            CP16(bo + p * PLANE_BY + lr0 * 80 + lc0 * 16,
                 src + (size_t)(rbase + lr0) * K + lc0 * 8);
            CP16(bo + p * PLANE_BY + lr1 * 80 + lc0 * 16,
                 src + (size_t)(rbase + lr1) * K + lc0 * 8);
        }
        CP_COMMIT();
    };

    load_chunk(0, 0);

    for (int c = 0; c < CHUNKS; c++) {
        CP_WAIT(0);            // chunk c's loads (only pending group) complete
        __syncthreads();       // also proves all warps done reading buffer (c+1)&1
        if (c + 1 < CHUNKS) load_chunk(c + 1, (c + 1) & 1);   // overlaps compute below

        const uint32_t bo = sbase + (c & 1) * BUF_BY;
        const uint32_t uAh = bo, uAl = bo + PLANE_BY;
        const uint32_t uBh = bo + 2 * PLANE_BY, uBl = bo + 3 * PLANE_BY;

#pragma unroll
        for (int ks = 0; ks < 32; ks += 16) {
            uint32_t bhi[4][2], blo[4][2];
#pragma unroll
            for (int p = 0; p < 2; p++) {
                int n = warp_n * 32 + p * 16 + (lane & 7) + ((lane >> 4) << 3);
                uint32_t off = (uint32_t)(n * LDA + ks + (((lane >> 3) & 1) << 3)) * 2;
                uint32_t r4[4];
                ldsm_x4(r4, uBh + off);
                bhi[2*p][0] = r4[0]; bhi[2*p][1] = r4[1];
                bhi[2*p+1][0] = r4[2]; bhi[2*p+1][1] = r4[3];
                ldsm_x4(r4, uBl + off);
                blo[2*p][0] = r4[0]; blo[2*p][1] = r4[1];
                blo[2*p+1][0] = r4[2]; blo[2*p+1][1] = r4[3];
            }
#pragma unroll
            for (int mt = 0; mt < 4; mt++) {
                int m = warp_m * 64 + mt * 16 + (lane & 15);
                uint32_t off = (uint32_t)(m * LDA + ks + ((lane >> 4) << 3)) * 2;
                uint32_t ahi[4], alo[4];
                ldsm_x4(ahi, uAh + off);
                ldsm_x4(alo, uAl + off);
#pragma unroll
                for (int nt = 0; nt < 4; nt++) {
                    mma_bf16(acc[mt][nt], ahi, bhi[nt]);
                    mma_bf16(acc[mt][nt], ahi, blo[nt]);
                    mma_bf16(acc[mt][nt], alo, bhi[nt]);
                }
            }
        }
        // no trailing barrier: next iteration's barrier provides the guarantee
    }

    // -------------------- epilogue --------------------
    const float inv_sqrt_s = 0.088388347648318447f;   // 1/sqrt(128)
    bf16* stH = (bf16*)smem;                          // v-transpose staging (aliased)
    bf16* stL = (bf16*)(smem + 128 * 136 * 2);
    if (MODE == 0) __syncthreads();                   // staging aliases pipeline buffers

#pragma unroll
    for (int mt = 0; mt < 4; mt++) {
#pragma unroll
        for (int nt = 0; nt < 4; nt++) {
            int mb = row0 + warp_m * 64 + mt * 16 + (lane >> 2);
            int nb = col0 + warp_n * 32 + nt * 8 + ((lane & 3) << 1);
#pragma unroll
            for (int h = 0; h < 2; h++) {
                int m = mb + 8 * h;
                int n = nb;
                float v0 = acc[mt][nt][h * 2 + 0];
                float v1 = acc[mt][nt][h * 2 + 1];
                if (MODE == 0) {
                    float s0 = v0 / (1.f + __expf(-v0));
                    float s1 = v1 / (1.f + __expf(-v1));
                    if (bx < 8) {                      // u (fp32)
                        *(float2*)(g_u + (size_t)m * EE + n) = make_float2(s0, s1);
                    } else if (bx < 16) {              // v -> stage transposed split
                        bf16 h0, l0, h1, l1;
                        split2(s0, h0, l0); split2(s1, h1, l1);
                        int nl = n - col0, ml = m - row0;
                        stH[nl * 136 + ml] = h0;       stL[nl * 136 + ml] = l0;
                        stH[(nl + 1) * 136 + ml] = h1; stL[(nl + 1) * 136 + ml] = l1;
                    } else {                           // q,k split
                        int s = n - 2 * EE;
                        uint32_t lo, hi;
                        size_t o = (size_t)m * SS + s;
                        hi = pksplit(fmaf(s0, e0[s], e1[s]), fmaf(s1, e0[s + 1], e1[s + 1]), lo);
                        *(uint32_t*)(g_q_h + o) = hi; *(uint32_t*)(g_q_l + o) = lo;
                        hi = pksplit(fmaf(s0, e0[SS + s], e1[SS + s]),
                                     fmaf(s1, e0[SS + s + 1], e1[SS + s + 1]), lo);
                        *(uint32_t*)(g_k_h + o) = hi; *(uint32_t*)(g_k_l + o) = lo;
                    }
                } else if (MODE == 1) {
                    float t0 = (v0 + e0[NN - 1 + n - m]) * inv_sqrt_s;     t0 = fmaxf(t0, 0.f);
                    float t1 = (v1 + e0[NN - 1 + n + 1 - m]) * inv_sqrt_s; t1 = fmaxf(t1, 0.f);
                    uint32_t lo, hi = pksplit(t0 * t0, t1 * t1, lo);
                    size_t o = ((size_t)b * NN + m) * NN + n;
                    *(uint32_t*)(g_attn_h + o) = hi;
                    *(uint32_t*)(g_attn_l + o) = lo;
                } else if (MODE == 2) {
                    size_t o = ((size_t)b * NN + m) * EE + n;
                    float2 uu = *(const float2*)(g_u + o);
                    uint32_t lo, hi = pksplit(uu.x * v0, uu.y * v1, lo);
                    *(uint32_t*)(g_mid_h + o) = hi;
                    *(uint32_t*)(g_mid_l + o) = lo;
                } else {
                    size_t o = (size_t)m * DD + n;
                    float2 xv = *(const float2*)(e0 + o);
                    *(float2*)(outp + o) = make_float2(fmaf(xv.x, e1[n], v0),
                                                       fmaf(xv.y, e1[n + 1], v1));
                }
            }
        }
    }

    // v-block: coalesced copy-out of staged transposed tile
    if (MODE == 0 && bx >= 8 && bx < 16) {
        __syncthreads();
        const int bb = row0 >> 10, mloc = row0 & (NN - 1);
        const int ebase = col0 - EE;
#pragma unroll
        for (int it = 0; it < 8; it++) {
            int id = tid + 256 * it;
            int el = id >> 4, mw = id & 15;
            size_t o = ((size_t)bb * EE + ebase + el) * NN + mloc + mw * 8;
            *(uint4*)(g_vt_h + o) = *(const uint4*)&stH[el * 136 + mw * 8];
            *(uint4*)(g_vt_l + o) = *(const uint4*)&stL[el * 136 + mw * 8];
        }
    }
}

// -------------------- launch --------------------
extern "C" void kernel_launch(void* const* d_in, const int* in_sizes, int n_in,
                              void* d_out, int out_size)
{
    const float* x     = (const float*)d_in[0];
    const float* w     = (const float*)d_in[1];
    const float* uvw   = (const float*)d_in[2];
    const float* ow    = (const float*)d_in[3];
    const float* gamma = (const float*)d_in[4];
    const float* beta  = (const float*)d_in[5];
    const float* g     = (const float*)d_in[6];
    const float* res   = (const float*)d_in[7];
    float* out = (float*)d_out;

    cudaFuncSetAttribute(gemm9<0>, cudaFuncAttributeMaxDynamicSharedMemorySize, SMEM_SZ);
    cudaFuncSetAttribute(gemm9<1>, cudaFuncAttributeMaxDynamicSharedMemorySize, SMEM_SZ);
    cudaFuncSetAttribute(gemm9<2>, cudaFuncAttributeMaxDynamicSharedMemorySize, SMEM_SZ);
    cudaFuncSetAttribute(gemm9<3>, cudaFuncAttributeMaxDynamicSharedMemorySize, SMEM_SZ);

    rownorm_split<<<ROWS / 8, 256>>>(x, g);
    wsplit<0><<<(UVC * DD + 255) / 256, 256>>>(uvw);
    wsplit<1><<<(DD * EE + 255) / 256, 256>>>(ow);

    gemm9<0><<<dim3(UVC / 128, ROWS / 128, 1), 256, SMEM_SZ>>>(gamma, beta, nullptr);
    gemm9<1><<<dim3(NN / 128, NN / 128, NB),   256, SMEM_SZ>>>(w, nullptr, nullptr);
    gemm9<2><<<dim3(EE / 128, NN / 128, NB),   256, SMEM_SZ>>>(nullptr, nullptr, nullptr);
    gemm9<3><<<dim3(DD / 128, ROWS / 128, 1),  256, SMEM_SZ>>>(x, res, out);
}